// round 1
// baseline (speedup 1.0000x reference)
#include <cuda_runtime.h>
#include <cuda_bf16.h>

// LocalDeepRFMFull: D=1024, D_r=256, B=4 stages, G=8, Ng=128, P=40, N=4096 rows.
// One CTA per row. x/z rows in smem with 32-float wrap pad (window base is
// (8g-16) mod 1024, width 40 -> reads up to index 1055). Thread t owns Wi row
// r=t (80 floats in registers, hoisted per stage). Per group: 20 LDS.128
// (broadcast) + 80 FFMA. h staged in 32-group smem chunks for the Wo reduce.

#define DD      1024
#define DRR     256
#define NSTAGE  4
#define GGRP    8
#define NGRP    128
#define PWIN    40
#define P2      80
#define TPB     256
#define GCHUNK  32

__global__ void __launch_bounds__(TPB, 2)
rfm_kernel(const float* __restrict__ x,
           const float* __restrict__ Wi,
           const float* __restrict__ bi,
           const float* __restrict__ Wo,
           float* __restrict__ out)
{
    __shared__ float x_s[DD + 32];
    __shared__ float z_s[DD + 32];
    __shared__ float zn_s[DD];
    __shared__ float h_s[GCHUNK][DRR];

    const int row = blockIdx.x;
    const int t   = threadIdx.x;

    // Load x row; z starts as x. Fill 32-float wrap pad.
    const float* xr = x + (size_t)row * DD;
    for (int j = t; j < DD; j += TPB) {
        float v = xr[j];
        x_s[j] = v;
        z_s[j] = v;
    }
    if (t < 32) {
        float v = xr[t];
        x_s[DD + t] = v;
        z_s[DD + t] = v;
    }
    __syncthreads();

    for (int s = 0; s < NSTAGE; ++s) {
        // Hoist this thread's Wi row (r = t) into registers: 80 floats.
        float w[P2];
        const float4* wrow = (const float4*)(Wi + ((size_t)(s * DRR + t)) * P2);
        #pragma unroll
        for (int k = 0; k < P2 / 4; ++k) {
            float4 v = wrow[k];
            w[4 * k + 0] = v.x;
            w[4 * k + 1] = v.y;
            w[4 * k + 2] = v.z;
            w[4 * k + 3] = v.w;
        }
        const float bias = bi[s * DRR + t];
        // Wo row used in the Z phase: c = t & 7 (L1-resident, 8 KB working set).
        const float4* worow = (const float4*)(Wo + ((size_t)(s * GGRP + (t & 7))) * DRR);

        for (int gc = 0; gc < NGRP; gc += GCHUNK) {
            // ---- h phase: thread t computes h[g][t] for 32 groups ----
            #pragma unroll 1
            for (int g = 0; g < GCHUNK; ++g) {
                const int base = (((gc + g) << 3) + (DD - 2 * GGRP)) & (DD - 1); // (8g-16) mod 1024, mult of 8
                const float4* xs4 = (const float4*)(x_s + base);
                const float4* zs4 = (const float4*)(z_s + base);
                float a0 = 0.f, a1 = 0.f, a2 = 0.f, a3 = 0.f;
                #pragma unroll
                for (int k = 0; k < PWIN / 4; ++k) {
                    float4 v = xs4[k];
                    a0 = fmaf(v.x, w[4 * k + 0], a0);
                    a1 = fmaf(v.y, w[4 * k + 1], a1);
                    a2 = fmaf(v.z, w[4 * k + 2], a2);
                    a3 = fmaf(v.w, w[4 * k + 3], a3);
                }
                #pragma unroll
                for (int k = 0; k < PWIN / 4; ++k) {
                    float4 v = zs4[k];
                    a0 = fmaf(v.x, w[PWIN + 4 * k + 0], a0);
                    a1 = fmaf(v.y, w[PWIN + 4 * k + 1], a1);
                    a2 = fmaf(v.z, w[PWIN + 4 * k + 2], a2);
                    a3 = fmaf(v.w, w[PWIN + 4 * k + 3], a3);
                }
                float acc = (a0 + a1) + (a2 + a3) + bias;
                // Accurate tanh (~1e-7 rel): tanh(x)=sign(x)*(1-e)/(1+e), e=exp(-2|x|).
                float ax = fabsf(acc);
                float e  = __expf(-2.0f * ax);
                float th = __fdividef(1.0f - e, 1.0f + e);
                th = copysignf(th, acc);
                h_s[g][t] = th;
            }
            __syncthreads();

            // ---- Z phase: thread t -> (group gl = t>>3 within chunk, col c = t&7) ----
            {
                const int gl = t >> 3;
                const float4* hrow = (const float4*)(h_s[gl]);
                float z0 = 0.f, z1 = 0.f, z2 = 0.f, z3 = 0.f;
                #pragma unroll
                for (int k = 0; k < DRR / 4; ++k) {
                    float4 hv = hrow[k];
                    float4 wv = worow[k];
                    z0 = fmaf(hv.x, wv.x, z0);
                    z1 = fmaf(hv.y, wv.y, z1);
                    z2 = fmaf(hv.z, wv.z, z2);
                    z3 = fmaf(hv.w, wv.w, z3);
                }
                zn_s[(gc << 3) + t] = (z0 + z1) + (z2 + z3);
            }
            __syncthreads();   // protects h_s reuse next chunk; last one orders zn_s
        }

        // z <- z_new (including wrap pad)
        for (int j = t; j < DD; j += TPB) z_s[j] = zn_s[j];
        if (t < 32) z_s[DD + t] = zn_s[t];
        __syncthreads();
    }

    float* orow = out + (size_t)row * DD;
    for (int j = t; j < DD; j += TPB) orow[j] = z_s[j];
}

extern "C" void kernel_launch(void* const* d_in, const int* in_sizes, int n_in,
                              void* d_out, int out_size)
{
    const float* x  = (const float*)d_in[0];   // [4096, 1024]
    const float* Wi = (const float*)d_in[1];   // [4, 256, 80]
    const float* bi = (const float*)d_in[2];   // [4, 256]
    const float* Wo = (const float*)d_in[3];   // [4, 8, 256]
    float* out = (float*)d_out;                // [4096, 1024]

    const int nrows = in_sizes[0] / DD;
    rfm_kernel<<<nrows, TPB>>>(x, Wi, bi, Wo, out);
}